// round 8
// baseline (speedup 1.0000x reference)
#include <cuda_runtime.h>
#include <stdint.h>

#define NMAX 100000
#define EMAX (NMAX * 16)

// Scratch (device globals — zero-initialized at load; no allocation allowed)
__device__ float    d_G[NMAX * 64];     // W_f @ f[n] + W_p @ node[n]
__device__ int      d_dst[EMAX];        // compacted int32 dst
__device__ unsigned d_maxk[NMAX * 64];  // fast: raw float bits; stray: enc keys
__device__ unsigned d_mink[NMAX * 64];
__device__ float    d_sum[64];
__device__ float    d_sumsq[64];
__device__ float    d_scale[64];
__device__ float    d_bias[64];
__device__ int      d_is64;
__device__ int      d_stray;

// Order-preserving float<->uint key (stray fallback only)
__device__ __forceinline__ unsigned enc(float f) {
    unsigned u = __float_as_uint(f);
    return (u & 0x80000000u) ? ~u : (u | 0x80000000u);
}
__device__ __forceinline__ float dec(unsigned k) {
    return __uint_as_float((k & 0x80000000u) ? (k ^ 0x80000000u) : ~k);
}

// ---------------------------------------------------------------------------
// Reset per-replay accumulators/flags (tiny; big clears only happen on stray).
__global__ void k_reset() {
    if (threadIdx.x < 64) { d_sum[threadIdx.x] = 0.f; d_sumsq[threadIdx.x] = 0.f; }
    if (threadIdx.x == 0) d_stray = 0;
}

// ---------------------------------------------------------------------------
// Compact edges: detect int64 vs int32 (high words of int64 indices < 2^31
// are zero; int32 layout has random dst there), write dst32, and verify the
// structured property src[e] == e % Nn. Incremental mod avoids divisions.
__global__ void k_conv(const void* __restrict__ edges, int Nn, long long Ne) {
    __shared__ int s_is64;
    if (threadIdx.x == 0) {
        const int* e32 = (const int*)edges;
        int bad = 0;
#pragma unroll
        for (int i = 1; i < 16; i += 2) bad |= e32[i];
        s_is64 = (bad == 0);
        if (blockIdx.x == 0) d_is64 = s_is64;
    }
    __syncthreads();
    const int is64 = s_is64;
    long long stride = (long long)gridDim.x * blockDim.x;
    long long t0 = (long long)blockIdx.x * blockDim.x + threadIdx.x;
    int r    = (int)(t0 % Nn);
    int smod = (int)(stride % Nn);
    int stray = 0;
    for (long long e = t0; e < Ne; e += stride) {
        int es, ed;
        if (is64) { longlong2 v = __ldg((const longlong2*)edges + e); es = (int)v.x; ed = (int)v.y; }
        else      { int2      v = __ldg((const int2*)edges + e);      es = v.x;      ed = v.y; }
        d_dst[e] = ed;
        stray |= (es != r);
        r += smod; if (r >= Nn) r -= Nn;
    }
    if (stray) d_stray = 1;
}

// Clear min/max key arrays — only needed on the stray fallback path.
__global__ void k_init(int n4) {
    if (!d_stray) return;
    int i = blockIdx.x * blockDim.x + threadIdx.x;
    if (i < n4) {
        ((uint4*)d_maxk)[i] = make_uint4(0u, 0u, 0u, 0u);
        ((uint4*)d_mink)[i] = make_uint4(~0u, ~0u, ~0u, ~0u);
    }
}

// ---------------------------------------------------------------------------
// Per-node precompute: G[n][j] = W_f@f[n] + W_p@node[n].  (P is rank-1 and is
// recomputed on the fly everywhere else.)  2-node ILP per thread.
__global__ void __launch_bounds__(256) k_pre(const float* __restrict__ nodep,
                                             const float* __restrict__ feat,
                                             const float* __restrict__ W, int Nn) {
    const int j = threadIdx.x & 63;
    float w[64];
#pragma unroll
    for (int i = 0; i < 64; i++) w[i] = __ldg(&W[j * 67 + i]);
    const float wp0 = __ldg(&W[j * 67 + 64]);
    const float wp1 = __ldg(&W[j * 67 + 65]);
    const float wp2 = __ldg(&W[j * 67 + 66]);
    int g  = (blockIdx.x * blockDim.x + threadIdx.x) >> 6;
    int gs = (gridDim.x * blockDim.x) >> 6;
    int half = (Nn + 1) >> 1;
    for (int m = g; m < half; m += gs) {
        int n0 = 2 * m;
        int n1c = min(2 * m + 1, Nn - 1);          // clamped (safe load)
        const float4* f0 = (const float4*)feat + (size_t)n0 * 16;
        const float4* f1 = (const float4*)feat + (size_t)n1c * 16;
        float a0 = 0.f, a1 = 0.f;
#pragma unroll
        for (int i4 = 0; i4 < 16; i4++) {
            float4 x = __ldg(&f0[i4]);
            float4 y = __ldg(&f1[i4]);
            a0 = fmaf(x.x, w[4*i4+0], a0); a1 = fmaf(y.x, w[4*i4+0], a1);
            a0 = fmaf(x.y, w[4*i4+1], a0); a1 = fmaf(y.y, w[4*i4+1], a1);
            a0 = fmaf(x.z, w[4*i4+2], a0); a1 = fmaf(y.z, w[4*i4+2], a1);
            a0 = fmaf(x.w, w[4*i4+3], a0); a1 = fmaf(y.w, w[4*i4+3], a1);
        }
        float p0 = wp0*__ldg(&nodep[3*n0])  + wp1*__ldg(&nodep[3*n0+1])  + wp2*__ldg(&nodep[3*n0+2]);
        float p1 = wp0*__ldg(&nodep[3*n1c]) + wp1*__ldg(&nodep[3*n1c+1]) + wp2*__ldg(&nodep[3*n1c+2]);
        d_G[(size_t)n0 * 64 + j] = a0 + p0;
        if (2 * m + 1 < Nn) d_G[(size_t)n1c * 64 + j] = a1 + p1;
    }
}

// ---------------------------------------------------------------------------
// FAST edge pass (structured src proven): 16 lanes = 1 node; lane cg owns
// channels 4cg..4cg+3. dst indices via L1-broadcast int32 loads (no shuffles).
// Each (n,cg) owned by exactly one thread -> plain float stores, no atomics.
__global__ void __launch_bounds__(256)
k_fast(const float* __restrict__ nodep, const float* __restrict__ W,
       int Nn, int kfull, int rem) {
    if (d_stray) return;
    __shared__ float s_sum[64];
    __shared__ float s_sq[64];
    if (threadIdx.x < 64) { s_sum[threadIdx.x] = 0.f; s_sq[threadIdx.x] = 0.f; }
    __syncthreads();
    const int lane = threadIdx.x & 31;
    const int cg   = lane & 15;
    // W_p coefficients for this lane's 4 channels
    float4 wx, wy, wz;
    wx.x = __ldg(&W[(4*cg+0)*67+64]); wy.x = __ldg(&W[(4*cg+0)*67+65]); wz.x = __ldg(&W[(4*cg+0)*67+66]);
    wx.y = __ldg(&W[(4*cg+1)*67+64]); wy.y = __ldg(&W[(4*cg+1)*67+65]); wz.y = __ldg(&W[(4*cg+1)*67+66]);
    wx.z = __ldg(&W[(4*cg+2)*67+64]); wy.z = __ldg(&W[(4*cg+2)*67+65]); wz.z = __ldg(&W[(4*cg+2)*67+66]);
    wx.w = __ldg(&W[(4*cg+3)*67+64]); wy.w = __ldg(&W[(4*cg+3)*67+65]); wz.w = __ldg(&W[(4*cg+3)*67+66]);
    const float4* G4 = (const float4*)d_G;
    const float INF = __int_as_float(0x7f800000);
    int gid = (blockIdx.x * blockDim.x + threadIdx.x) >> 4;
    int gs  = (gridDim.x * blockDim.x) >> 4;
    float4 sum = make_float4(0.f,0.f,0.f,0.f);
    float4 sq  = make_float4(0.f,0.f,0.f,0.f);
    for (int n = gid; n < Nn; n += gs) {
        float nx = __ldg(&nodep[3*n]), ny = __ldg(&nodep[3*n+1]), nz = __ldg(&nodep[3*n+2]);
        float4 p;
        p.x = fmaf(wx.x, nx, fmaf(wy.x, ny, wz.x * nz));
        p.y = fmaf(wx.y, nx, fmaf(wy.y, ny, wz.y * nz));
        p.z = fmaf(wx.z, nx, fmaf(wy.z, ny, wz.z * nz));
        p.w = fmaf(wx.w, nx, fmaf(wy.w, ny, wz.w * nz));
        int kmax = kfull + (n < rem);
        float4 mx = make_float4(-INF,-INF,-INF,-INF);
        float4 mn = make_float4( INF, INF, INF, INF);
#pragma unroll 8
        for (int k = 0; k < kmax; k++) {
            int dk = __ldg(&d_dst[n + k * Nn]);          // broadcast, L1
            float4 g = __ldg(&G4[(size_t)dk * 16 + cg]); // 256B/edge, L2
            float dx = g.x - p.x, dy = g.y - p.y, dz = g.z - p.z, dw = g.w - p.w;
            sum.x += dx; sum.y += dy; sum.z += dz; sum.w += dw;
            sq.x = fmaf(dx,dx,sq.x); sq.y = fmaf(dy,dy,sq.y);
            sq.z = fmaf(dz,dz,sq.z); sq.w = fmaf(dw,dw,sq.w);
            mx.x = fmaxf(mx.x,dx); mx.y = fmaxf(mx.y,dy);
            mx.z = fmaxf(mx.z,dz); mx.w = fmaxf(mx.w,dw);
            mn.x = fminf(mn.x,dx); mn.y = fminf(mn.y,dy);
            mn.z = fminf(mn.z,dz); mn.w = fminf(mn.w,dw);
        }
        ((float4*)d_maxk)[(size_t)n * 16 + cg] = mx;     // exclusive owner: no atomics
        ((float4*)d_mink)[(size_t)n * 16 + cg] = mn;
    }
    __syncwarp();
#define RED16(v) v += __shfl_xor_sync(0xFFFFFFFFu, v, 16)
    RED16(sum.x); RED16(sum.y); RED16(sum.z); RED16(sum.w);
    RED16(sq.x);  RED16(sq.y);  RED16(sq.z);  RED16(sq.w);
    if ((lane & 16) == 0) {
        atomicAdd(&s_sum[4*cg+0], sum.x); atomicAdd(&s_sum[4*cg+1], sum.y);
        atomicAdd(&s_sum[4*cg+2], sum.z); atomicAdd(&s_sum[4*cg+3], sum.w);
        atomicAdd(&s_sq[4*cg+0], sq.x);   atomicAdd(&s_sq[4*cg+1], sq.y);
        atomicAdd(&s_sq[4*cg+2], sq.z);   atomicAdd(&s_sq[4*cg+3], sq.w);
    }
    __syncthreads();
    if (threadIdx.x < 64)       atomicAdd(&d_sum[threadIdx.x], s_sum[threadIdx.x]);
    else if (threadIdx.x < 128) atomicAdd(&d_sumsq[threadIdx.x - 64], s_sq[threadIdx.x - 64]);
}

// ---------------------------------------------------------------------------
// STRAY fallback (arbitrary edges): shuffle-distributed edges, enc-key atomics.
// Dormant on structured data; kept for correctness.
__global__ void __launch_bounds__(256)
k_stray(const void* __restrict__ edges, const float* __restrict__ nodep,
        const float* __restrict__ W, int Nn, long long Ne) {
    if (!d_stray) return;
    __shared__ float s_sum[64];
    __shared__ float s_sq[64];
    if (threadIdx.x < 64) { s_sum[threadIdx.x] = 0.f; s_sq[threadIdx.x] = 0.f; }
    __syncthreads();
    const int lane = threadIdx.x & 31;
    const int cg   = lane & 15;
    const int half = lane & 16;
    const unsigned hm = 0xFFFFu << half;
    const int is64 = d_is64;
    float4 wx, wy, wz;
    wx.x = __ldg(&W[(4*cg+0)*67+64]); wy.x = __ldg(&W[(4*cg+0)*67+65]); wz.x = __ldg(&W[(4*cg+0)*67+66]);
    wx.y = __ldg(&W[(4*cg+1)*67+64]); wy.y = __ldg(&W[(4*cg+1)*67+65]); wz.y = __ldg(&W[(4*cg+1)*67+66]);
    wx.z = __ldg(&W[(4*cg+2)*67+64]); wy.z = __ldg(&W[(4*cg+2)*67+65]); wz.z = __ldg(&W[(4*cg+2)*67+66]);
    wx.w = __ldg(&W[(4*cg+3)*67+64]); wy.w = __ldg(&W[(4*cg+3)*67+65]); wz.w = __ldg(&W[(4*cg+3)*67+66]);
    const float4* G4 = (const float4*)d_G;
    const float INF = __int_as_float(0x7f800000);
    int gid = (blockIdx.x * blockDim.x + threadIdx.x) >> 4;
    int gs  = (gridDim.x * blockDim.x) >> 4;
    float4 sum = make_float4(0.f,0.f,0.f,0.f);
    float4 sq  = make_float4(0.f,0.f,0.f,0.f);
    for (int n = gid; n < Nn; n += gs) {
        long long e = (long long)n + (long long)cg * Nn;
        int es = 0, ed = 0;
        if (e < Ne) {
            if (is64) { longlong2 t = __ldg((const longlong2*)edges + e); es = (int)t.x; ed = (int)t.y; }
            else      { int2      t = __ldg((const int2*)edges + e);      es = t.x;      ed = t.y; }
        }
        float nx = __ldg(&nodep[3*n]), ny = __ldg(&nodep[3*n+1]), nz = __ldg(&nodep[3*n+2]);
        float4 pn;
        pn.x = fmaf(wx.x, nx, fmaf(wy.x, ny, wz.x * nz));
        pn.y = fmaf(wx.y, nx, fmaf(wy.y, ny, wz.y * nz));
        pn.z = fmaf(wx.z, nx, fmaf(wy.z, ny, wz.z * nz));
        pn.w = fmaf(wx.w, nx, fmaf(wy.w, ny, wz.w * nz));
        int kmax = (int)((Ne - n + Nn - 1) / Nn);
        kmax = kmax > 16 ? 16 : kmax;
        float4 hmx = make_float4(-INF,-INF,-INF,-INF);
        float4 hmn = make_float4( INF, INF, INF, INF);
#pragma unroll
        for (int k = 0; k < 16; k++) {
            if (k >= kmax) break;
            int sk = __shfl_sync(hm, es, half + k);
            int dk = __shfl_sync(hm, ed, half + k);
            float4 g = __ldg(&G4[(size_t)dk * 16 + cg]);
            float4 p = pn;
            if (sk != n) {
                float sx = __ldg(&nodep[3*sk]), sy = __ldg(&nodep[3*sk+1]), sz = __ldg(&nodep[3*sk+2]);
                p.x = fmaf(wx.x, sx, fmaf(wy.x, sy, wz.x * sz));
                p.y = fmaf(wx.y, sx, fmaf(wy.y, sy, wz.y * sz));
                p.z = fmaf(wx.z, sx, fmaf(wy.z, sy, wz.z * sz));
                p.w = fmaf(wx.w, sx, fmaf(wy.w, sy, wz.w * sz));
            }
            float dx = g.x - p.x, dy = g.y - p.y, dz = g.z - p.z, dw = g.w - p.w;
            sum.x += dx; sum.y += dy; sum.z += dz; sum.w += dw;
            sq.x = fmaf(dx,dx,sq.x); sq.y = fmaf(dy,dy,sq.y);
            sq.z = fmaf(dz,dz,sq.z); sq.w = fmaf(dw,dw,sq.w);
            if (sk == n) {
                hmx.x = fmaxf(hmx.x,dx); hmx.y = fmaxf(hmx.y,dy);
                hmx.z = fmaxf(hmx.z,dz); hmx.w = fmaxf(hmx.w,dw);
                hmn.x = fminf(hmn.x,dx); hmn.y = fminf(hmn.y,dy);
                hmn.z = fminf(hmn.z,dz); hmn.w = fminf(hmn.w,dw);
            } else {
                unsigned* mo = d_maxk + (size_t)sk * 64 + cg * 4;
                unsigned* no = d_mink + (size_t)sk * 64 + cg * 4;
                atomicMax(mo+0, enc(dx)); atomicMin(no+0, enc(dx));
                atomicMax(mo+1, enc(dy)); atomicMin(no+1, enc(dy));
                atomicMax(mo+2, enc(dz)); atomicMin(no+2, enc(dz));
                atomicMax(mo+3, enc(dw)); atomicMin(no+3, enc(dw));
            }
        }
        unsigned* mo = d_maxk + (size_t)n * 64 + cg * 4;
        unsigned* no = d_mink + (size_t)n * 64 + cg * 4;
        atomicMax(mo+0, enc(hmx.x)); atomicMin(no+0, enc(hmn.x));
        atomicMax(mo+1, enc(hmx.y)); atomicMin(no+1, enc(hmn.y));
        atomicMax(mo+2, enc(hmx.z)); atomicMin(no+2, enc(hmn.z));
        atomicMax(mo+3, enc(hmx.w)); atomicMin(no+3, enc(hmn.w));
    }
    __syncwarp();
    RED16(sum.x); RED16(sum.y); RED16(sum.z); RED16(sum.w);
    RED16(sq.x);  RED16(sq.y);  RED16(sq.z);  RED16(sq.w);
    if (half == 0) {
        atomicAdd(&s_sum[4*cg+0], sum.x); atomicAdd(&s_sum[4*cg+1], sum.y);
        atomicAdd(&s_sum[4*cg+2], sum.z); atomicAdd(&s_sum[4*cg+3], sum.w);
        atomicAdd(&s_sq[4*cg+0], sq.x);   atomicAdd(&s_sq[4*cg+1], sq.y);
        atomicAdd(&s_sq[4*cg+2], sq.z);   atomicAdd(&s_sq[4*cg+3], sq.w);
    }
    __syncthreads();
    if (threadIdx.x < 64)       atomicAdd(&d_sum[threadIdx.x], s_sum[threadIdx.x]);
    else if (threadIdx.x < 128) atomicAdd(&d_sumsq[threadIdx.x - 64], s_sq[threadIdx.x - 64]);
}

__global__ void k_fin(const float* __restrict__ gamma,
                      const float* __restrict__ beta, float invNe) {
    int j = threadIdx.x;
    float mean = d_sum[j] * invNe;
    float var  = d_sumsq[j] * invNe - mean * mean;
    var = var > 0.f ? var : 0.f;
    float s = __ldg(&gamma[j]) * rsqrtf(var + 1e-5f);
    d_scale[j] = s;
    d_bias[j]  = __ldg(&beta[j]) - mean * s;
}

// ---------------------------------------------------------------------------
// Finalize: y = relu(extreme(h)*s + b); monotone affine+relu commutes with
// max. Zero-edge nodes: ±inf/NaN collapse to 0 via fmaxf.
__global__ void k_outfin(float* __restrict__ out, int Nn) {
    int t = blockIdx.x * blockDim.x + threadIdx.x;
    if (t >= Nn * 16) return;
    int cg = t & 15;
    int stray = d_stray;
    float4 sc = *(const float4*)(d_scale + cg * 4);
    float4 bs = *(const float4*)(d_bias + cg * 4);
    uint4 mk = ((const uint4*)d_maxk)[t];
    uint4 nk = ((const uint4*)d_mink)[t];
    float mxx, mxy, mxz, mxw, mnx, mny, mnz, mnw;
    if (stray) {
        mxx = dec(mk.x); mxy = dec(mk.y); mxz = dec(mk.z); mxw = dec(mk.w);
        mnx = dec(nk.x); mny = dec(nk.y); mnz = dec(nk.z); mnw = dec(nk.w);
    } else {
        mxx = __uint_as_float(mk.x); mxy = __uint_as_float(mk.y);
        mxz = __uint_as_float(mk.z); mxw = __uint_as_float(mk.w);
        mnx = __uint_as_float(nk.x); mny = __uint_as_float(nk.y);
        mnz = __uint_as_float(nk.z); mnw = __uint_as_float(nk.w);
    }
    float4 y;
    y.x = fmaxf(fmaf((sc.x >= 0.f) ? mxx : mnx, sc.x, bs.x), 0.f);
    y.y = fmaxf(fmaf((sc.y >= 0.f) ? mxy : mny, sc.y, bs.y), 0.f);
    y.z = fmaxf(fmaf((sc.z >= 0.f) ? mxz : mnz, sc.z, bs.z), 0.f);
    y.w = fmaxf(fmaf((sc.w >= 0.f) ? mxw : mnw, sc.w, bs.w), 0.f);
    ((float4*)out)[t] = y;
}

// ---------------------------------------------------------------------------
extern "C" void kernel_launch(void* const* d_in, const int* in_sizes, int n_in,
                              void* d_out, int out_size) {
    const float* nodep = (const float*)d_in[0];  // (Nn, 3)
    const float* feat  = (const float*)d_in[1];  // (Nn, 64)
    const float* W     = (const float*)d_in[2];  // (64, 67)
    const float* gamma = (const float*)d_in[3];  // (64,)
    const float* beta  = (const float*)d_in[4];  // (64,)
    const void*  edges = d_in[5];                // (Ne, 2) int32 or int64

    int       Nn = in_sizes[0] / 3;
    long long Ne = (long long)in_sizes[5] / 2;
    float*    out = (float*)d_out;
    int kfull = (int)(Ne / Nn);
    int rem   = (int)(Ne % Nn);
    int n4    = (Nn * 64) / 4;

    k_reset <<<1, 64>>>();
    k_conv  <<<1184, 256>>>(edges, Nn, Ne);
    k_init  <<<(n4 + 255) / 256, 256>>>(n4);
    k_pre   <<<1184, 256>>>(nodep, feat, W, Nn);
    k_fast  <<<1184, 256>>>(nodep, W, Nn, kfull, rem);
    k_stray <<<1184, 256>>>(edges, nodep, W, Nn, Ne);
    k_fin   <<<1, 64>>>(gamma, beta, 1.0f / (float)Ne);
    k_outfin<<<(Nn * 16 + 255) / 256, 256>>>(out, Nn);
}

// round 10
// speedup vs baseline: 2.0640x; 2.0640x over previous
#include <cuda_runtime.h>
#include <stdint.h>

#define NMAX 100000
#define EMAX (NMAX * 16)

// Scratch (device globals — no allocation allowed)
__device__ float    d_G[NMAX * 64];     // W_f @ f[n] + W_p @ node[n]
__device__ int      d_dst[EMAX];        // compacted int32 dst
__device__ unsigned d_maxk[NMAX * 64];  // fast: raw float bits; stray: enc keys
__device__ unsigned d_mink[NMAX * 64];
__device__ float    d_sum[64];
__device__ float    d_sumsq[64];
__device__ float    d_scale[64];
__device__ float    d_bias[64];
__device__ int      d_is64;
__device__ int      d_stray;

// Order-preserving float<->uint key (stray fallback only)
__device__ __forceinline__ unsigned enc(float f) {
    unsigned u = __float_as_uint(f);
    return (u & 0x80000000u) ? ~u : (u | 0x80000000u);
}
__device__ __forceinline__ float dec(unsigned k) {
    return __uint_as_float((k & 0x80000000u) ? (k ^ 0x80000000u) : ~k);
}

// fma of scalar into float4 channel vector (function, not macro: hygiene)
__device__ __forceinline__ void fma4(float4& acc, float f, const float4& wv) {
    acc.x = fmaf(f, wv.x, acc.x);
    acc.y = fmaf(f, wv.y, acc.y);
    acc.z = fmaf(f, wv.z, acc.z);
    acc.w = fmaf(f, wv.w, acc.w);
}

// ---------------------------------------------------------------------------
__global__ void k_reset() {
    if (threadIdx.x < 64) { d_sum[threadIdx.x] = 0.f; d_sumsq[threadIdx.x] = 0.f; }
    if (threadIdx.x == 0) d_stray = 0;
}

// ---------------------------------------------------------------------------
// Compact edges to int32 dst; detect int64 vs int32 (int64 high words of
// values < 2^31 are zero); verify structured src[e] == e % Nn (no divisions).
__global__ void k_conv(const void* __restrict__ edges, int Nn, long long Ne) {
    __shared__ int s_is64;
    if (threadIdx.x == 0) {
        const int* e32 = (const int*)edges;
        int bad = 0;
#pragma unroll
        for (int i = 1; i < 16; i += 2) bad |= e32[i];
        s_is64 = (bad == 0);
        if (blockIdx.x == 0) d_is64 = s_is64;
    }
    __syncthreads();
    const int is64 = s_is64;
    long long stride = (long long)gridDim.x * blockDim.x;
    long long t0 = (long long)blockIdx.x * blockDim.x + threadIdx.x;
    int r    = (int)(t0 % Nn);
    int smod = (int)(stride % Nn);
    int stray = 0;
    for (long long e = t0; e < Ne; e += stride) {
        int es, ed;
        if (is64) { longlong2 v = __ldg((const longlong2*)edges + e); es = (int)v.x; ed = (int)v.y; }
        else      { int2      v = __ldg((const int2*)edges + e);      es = v.x;      ed = v.y; }
        d_dst[e] = ed;
        stray |= (es != r);
        r += smod; if (r >= Nn) r -= Nn;
    }
    if (stray) d_stray = 1;
}

// Clear min/max key arrays — only needed on the stray fallback path.
__global__ void k_init(int n4) {
    if (!d_stray) return;
    int i = blockIdx.x * blockDim.x + threadIdx.x;
    if (i < n4) {
        ((uint4*)d_maxk)[i] = make_uint4(0u, 0u, 0u, 0u);
        ((uint4*)d_mink)[i] = make_uint4(~0u, ~0u, ~0u, ~0u);
    }
}

// ---------------------------------------------------------------------------
// k_pre as a smem-tiled GEMM. W transposed into smem as Ws[i][c]; thread
// tile = 4 nodes x 4 channels (16 fp32 accumulators); 64 FMA per 8 loads.
// Block = 256 threads = 16 channel-groups x 16 node-slots -> 64 nodes/block.
__global__ void __launch_bounds__(256) k_pre(const float* __restrict__ nodep,
                                             const float* __restrict__ feat,
                                             const float* __restrict__ W, int Nn) {
    __shared__ float Ws[64 * 64];   // Ws[i*64 + c]
    __shared__ float Wp[3 * 64];    // Wp[r*64 + c]
    for (int idx = threadIdx.x; idx < 64 * 67; idx += 256) {
        int c = idx / 67, k = idx - c * 67;
        float v = __ldg(&W[idx]);
        if (k < 64) Ws[k * 64 + c] = v;
        else        Wp[(k - 64) * 64 + c] = v;
    }
    __syncthreads();
    const int cg   = threadIdx.x & 15;    // channels 4cg..4cg+3
    const int slot = threadIdx.x >> 4;    // node slot (16 per block)
    const float4* WsT = (const float4*)Ws;

    int n0 = blockIdx.x * 64 + slot * 4;
    if (n0 >= Nn) return;
    int na = n0;
    int nb = min(n0 + 1, Nn - 1);
    int nc = min(n0 + 2, Nn - 1);
    int nd = min(n0 + 3, Nn - 1);
    const float4* fA = (const float4*)(feat + (size_t)na * 64);
    const float4* fB = (const float4*)(feat + (size_t)nb * 64);
    const float4* fC = (const float4*)(feat + (size_t)nc * 64);
    const float4* fD = (const float4*)(feat + (size_t)nd * 64);
    float4 accA = make_float4(0.f,0.f,0.f,0.f);
    float4 accB = make_float4(0.f,0.f,0.f,0.f);
    float4 accC = make_float4(0.f,0.f,0.f,0.f);
    float4 accD = make_float4(0.f,0.f,0.f,0.f);
#pragma unroll
    for (int i4 = 0; i4 < 16; i4++) {
        float4 a = __ldg(&fA[i4]);
        float4 b = __ldg(&fB[i4]);
        float4 c = __ldg(&fC[i4]);
        float4 d = __ldg(&fD[i4]);
        float4 w0 = WsT[(4*i4+0)*16 + cg];
        float4 w1 = WsT[(4*i4+1)*16 + cg];
        float4 w2 = WsT[(4*i4+2)*16 + cg];
        float4 w3 = WsT[(4*i4+3)*16 + cg];
        fma4(accA, a.x, w0); fma4(accA, a.y, w1); fma4(accA, a.z, w2); fma4(accA, a.w, w3);
        fma4(accB, b.x, w0); fma4(accB, b.y, w1); fma4(accB, b.z, w2); fma4(accB, b.w, w3);
        fma4(accC, c.x, w0); fma4(accC, c.y, w1); fma4(accC, c.z, w2); fma4(accC, c.w, w3);
        fma4(accD, d.x, w0); fma4(accD, d.y, w1); fma4(accD, d.z, w2); fma4(accD, d.w, w3);
    }
    // + W_p @ node (rank-1 position part)
    float4 wpx = ((const float4*)(Wp +   0))[cg];
    float4 wpy = ((const float4*)(Wp +  64))[cg];
    float4 wpz = ((const float4*)(Wp + 128))[cg];
    {
        float x0 = __ldg(&nodep[3*na]), y0 = __ldg(&nodep[3*na+1]), z0 = __ldg(&nodep[3*na+2]);
        fma4(accA, x0, wpx); fma4(accA, y0, wpy); fma4(accA, z0, wpz);
        float x1 = __ldg(&nodep[3*nb]), y1 = __ldg(&nodep[3*nb+1]), z1 = __ldg(&nodep[3*nb+2]);
        fma4(accB, x1, wpx); fma4(accB, y1, wpy); fma4(accB, z1, wpz);
        float x2 = __ldg(&nodep[3*nc]), y2 = __ldg(&nodep[3*nc+1]), z2 = __ldg(&nodep[3*nc+2]);
        fma4(accC, x2, wpx); fma4(accC, y2, wpy); fma4(accC, z2, wpz);
        float x3 = __ldg(&nodep[3*nd]), y3 = __ldg(&nodep[3*nd+1]), z3 = __ldg(&nodep[3*nd+2]);
        fma4(accD, x3, wpx); fma4(accD, y3, wpy); fma4(accD, z3, wpz);
    }
    float4* G4 = (float4*)d_G;
    G4[(size_t)n0 * 16 + cg] = accA;
    if (n0 + 1 < Nn) G4[(size_t)(n0+1) * 16 + cg] = accB;
    if (n0 + 2 < Nn) G4[(size_t)(n0+2) * 16 + cg] = accC;
    if (n0 + 3 < Nn) G4[(size_t)(n0+3) * 16 + cg] = accD;
}

// ---------------------------------------------------------------------------
// FAST edge pass (structured src proven): 16 lanes = 1 node; lane cg owns
// channels 4cg..4cg+3. kmax==16 path prefetches all dst indices then issues
// 16 independent float4 gathers (MLP=16). Exclusive ownership -> plain stores.
__global__ void __launch_bounds__(256)
k_fast(const float* __restrict__ nodep, const float* __restrict__ W,
       int Nn, int kfull, int rem) {
    if (d_stray) return;
    __shared__ float s_sum[64];
    __shared__ float s_sq[64];
    if (threadIdx.x < 64) { s_sum[threadIdx.x] = 0.f; s_sq[threadIdx.x] = 0.f; }
    __syncthreads();
    const int lane = threadIdx.x & 31;
    const int cg   = lane & 15;
    float4 wx, wy, wz;
    wx.x = __ldg(&W[(4*cg+0)*67+64]); wy.x = __ldg(&W[(4*cg+0)*67+65]); wz.x = __ldg(&W[(4*cg+0)*67+66]);
    wx.y = __ldg(&W[(4*cg+1)*67+64]); wy.y = __ldg(&W[(4*cg+1)*67+65]); wz.y = __ldg(&W[(4*cg+1)*67+66]);
    wx.z = __ldg(&W[(4*cg+2)*67+64]); wy.z = __ldg(&W[(4*cg+2)*67+65]); wz.z = __ldg(&W[(4*cg+2)*67+66]);
    wx.w = __ldg(&W[(4*cg+3)*67+64]); wy.w = __ldg(&W[(4*cg+3)*67+65]); wz.w = __ldg(&W[(4*cg+3)*67+66]);
    const float4* G4 = (const float4*)d_G;
    const float INF = __int_as_float(0x7f800000);
    int gid = (blockIdx.x * blockDim.x + threadIdx.x) >> 4;
    int gs  = (gridDim.x * blockDim.x) >> 4;
    float4 sum = make_float4(0.f,0.f,0.f,0.f);
    float4 sq  = make_float4(0.f,0.f,0.f,0.f);
    for (int n = gid; n < Nn; n += gs) {
        float nx = __ldg(&nodep[3*n]), ny = __ldg(&nodep[3*n+1]), nz = __ldg(&nodep[3*n+2]);
        float4 p;
        p.x = fmaf(wx.x, nx, fmaf(wy.x, ny, wz.x * nz));
        p.y = fmaf(wx.y, nx, fmaf(wy.y, ny, wz.y * nz));
        p.z = fmaf(wx.z, nx, fmaf(wy.z, ny, wz.z * nz));
        p.w = fmaf(wx.w, nx, fmaf(wy.w, ny, wz.w * nz));
        int kmax = kfull + (n < rem);
        float4 mx = make_float4(-INF,-INF,-INF,-INF);
        float4 mn = make_float4( INF, INF, INF, INF);
#define EDGE_BODY(G) { \
            float dx = G.x - p.x, dy = G.y - p.y, dz = G.z - p.z, dw = G.w - p.w; \
            sum.x += dx; sum.y += dy; sum.z += dz; sum.w += dw; \
            sq.x = fmaf(dx,dx,sq.x); sq.y = fmaf(dy,dy,sq.y); \
            sq.z = fmaf(dz,dz,sq.z); sq.w = fmaf(dw,dw,sq.w); \
            mx.x = fmaxf(mx.x,dx); mx.y = fmaxf(mx.y,dy); \
            mx.z = fmaxf(mx.z,dz); mx.w = fmaxf(mx.w,dw); \
            mn.x = fminf(mn.x,dx); mn.y = fminf(mn.y,dy); \
            mn.z = fminf(mn.z,dz); mn.w = fminf(mn.w,dw); }
        if (kmax == 16) {
            int dk[16];
#pragma unroll
            for (int k = 0; k < 16; k++) dk[k] = __ldg(&d_dst[n + k * Nn]);
#pragma unroll
            for (int k = 0; k < 16; k++) {
                float4 g = __ldg(&G4[(size_t)dk[k] * 16 + cg]);
                EDGE_BODY(g);
            }
        } else {
            for (int k = 0; k < kmax; k++) {
                int dk = __ldg(&d_dst[n + k * Nn]);
                float4 g = __ldg(&G4[(size_t)dk * 16 + cg]);
                EDGE_BODY(g);
            }
        }
        ((float4*)d_maxk)[(size_t)n * 16 + cg] = mx;
        ((float4*)d_mink)[(size_t)n * 16 + cg] = mn;
    }
    __syncwarp();
#define RED16(v) v += __shfl_xor_sync(0xFFFFFFFFu, v, 16)
    RED16(sum.x); RED16(sum.y); RED16(sum.z); RED16(sum.w);
    RED16(sq.x);  RED16(sq.y);  RED16(sq.z);  RED16(sq.w);
    if ((lane & 16) == 0) {
        atomicAdd(&s_sum[4*cg+0], sum.x); atomicAdd(&s_sum[4*cg+1], sum.y);
        atomicAdd(&s_sum[4*cg+2], sum.z); atomicAdd(&s_sum[4*cg+3], sum.w);
        atomicAdd(&s_sq[4*cg+0], sq.x);   atomicAdd(&s_sq[4*cg+1], sq.y);
        atomicAdd(&s_sq[4*cg+2], sq.z);   atomicAdd(&s_sq[4*cg+3], sq.w);
    }
    __syncthreads();
    if (threadIdx.x < 64)       atomicAdd(&d_sum[threadIdx.x], s_sum[threadIdx.x]);
    else if (threadIdx.x < 128) atomicAdd(&d_sumsq[threadIdx.x - 64], s_sq[threadIdx.x - 64]);
}

// ---------------------------------------------------------------------------
// STRAY fallback (arbitrary edges): shuffle-distributed edges, enc-key
// atomics. Dormant on structured data; kept for correctness.
__global__ void __launch_bounds__(256)
k_stray(const void* __restrict__ edges, const float* __restrict__ nodep,
        const float* __restrict__ W, int Nn, long long Ne) {
    if (!d_stray) return;
    __shared__ float s_sum[64];
    __shared__ float s_sq[64];
    if (threadIdx.x < 64) { s_sum[threadIdx.x] = 0.f; s_sq[threadIdx.x] = 0.f; }
    __syncthreads();
    const int lane = threadIdx.x & 31;
    const int cg   = lane & 15;
    const int half = lane & 16;
    const unsigned hm = 0xFFFFu << half;
    const int is64 = d_is64;
    float4 wx, wy, wz;
    wx.x = __ldg(&W[(4*cg+0)*67+64]); wy.x = __ldg(&W[(4*cg+0)*67+65]); wz.x = __ldg(&W[(4*cg+0)*67+66]);
    wx.y = __ldg(&W[(4*cg+1)*67+64]); wy.y = __ldg(&W[(4*cg+1)*67+65]); wz.y = __ldg(&W[(4*cg+1)*67+66]);
    wx.z = __ldg(&W[(4*cg+2)*67+64]); wy.z = __ldg(&W[(4*cg+2)*67+65]); wz.z = __ldg(&W[(4*cg+2)*67+66]);
    wx.w = __ldg(&W[(4*cg+3)*67+64]); wy.w = __ldg(&W[(4*cg+3)*67+65]); wz.w = __ldg(&W[(4*cg+3)*67+66]);
    const float4* G4 = (const float4*)d_G;
    const float INF = __int_as_float(0x7f800000);
    int gid = (blockIdx.x * blockDim.x + threadIdx.x) >> 4;
    int gs  = (gridDim.x * blockDim.x) >> 4;
    float4 sum = make_float4(0.f,0.f,0.f,0.f);
    float4 sq  = make_float4(0.f,0.f,0.f,0.f);
    for (int n = gid; n < Nn; n += gs) {
        long long e = (long long)n + (long long)cg * Nn;
        int es = 0, ed = 0;
        if (e < Ne) {
            if (is64) { longlong2 t = __ldg((const longlong2*)edges + e); es = (int)t.x; ed = (int)t.y; }
            else      { int2      t = __ldg((const int2*)edges + e);      es = t.x;      ed = t.y; }
        }
        float nx = __ldg(&nodep[3*n]), ny = __ldg(&nodep[3*n+1]), nz = __ldg(&nodep[3*n+2]);
        float4 pn;
        pn.x = fmaf(wx.x, nx, fmaf(wy.x, ny, wz.x * nz));
        pn.y = fmaf(wx.y, nx, fmaf(wy.y, ny, wz.y * nz));
        pn.z = fmaf(wx.z, nx, fmaf(wy.z, ny, wz.z * nz));
        pn.w = fmaf(wx.w, nx, fmaf(wy.w, ny, wz.w * nz));
        int kmax = (int)((Ne - n + Nn - 1) / Nn);
        kmax = kmax > 16 ? 16 : kmax;
        float4 hmx = make_float4(-INF,-INF,-INF,-INF);
        float4 hmn = make_float4( INF, INF, INF, INF);
#pragma unroll
        for (int k = 0; k < 16; k++) {
            if (k >= kmax) break;
            int sk = __shfl_sync(hm, es, half + k);
            int dk = __shfl_sync(hm, ed, half + k);
            float4 g = __ldg(&G4[(size_t)dk * 16 + cg]);
            float4 p = pn;
            if (sk != n) {
                float sx = __ldg(&nodep[3*sk]), sy = __ldg(&nodep[3*sk+1]), sz = __ldg(&nodep[3*sk+2]);
                p.x = fmaf(wx.x, sx, fmaf(wy.x, sy, wz.x * sz));
                p.y = fmaf(wx.y, sx, fmaf(wy.y, sy, wz.y * sz));
                p.z = fmaf(wx.z, sx, fmaf(wy.z, sy, wz.z * sz));
                p.w = fmaf(wx.w, sx, fmaf(wy.w, sy, wz.w * sz));
            }
            float dx = g.x - p.x, dy = g.y - p.y, dz = g.z - p.z, dw = g.w - p.w;
            sum.x += dx; sum.y += dy; sum.z += dz; sum.w += dw;
            sq.x = fmaf(dx,dx,sq.x); sq.y = fmaf(dy,dy,sq.y);
            sq.z = fmaf(dz,dz,sq.z); sq.w = fmaf(dw,dw,sq.w);
            if (sk == n) {
                hmx.x = fmaxf(hmx.x,dx); hmx.y = fmaxf(hmx.y,dy);
                hmx.z = fmaxf(hmx.z,dz); hmx.w = fmaxf(hmx.w,dw);
                hmn.x = fminf(hmn.x,dx); hmn.y = fminf(hmn.y,dy);
                hmn.z = fminf(hmn.z,dz); hmn.w = fminf(hmn.w,dw);
            } else {
                unsigned* mo = d_maxk + (size_t)sk * 64 + cg * 4;
                unsigned* no = d_mink + (size_t)sk * 64 + cg * 4;
                atomicMax(mo+0, enc(dx)); atomicMin(no+0, enc(dx));
                atomicMax(mo+1, enc(dy)); atomicMin(no+1, enc(dy));
                atomicMax(mo+2, enc(dz)); atomicMin(no+2, enc(dz));
                atomicMax(mo+3, enc(dw)); atomicMin(no+3, enc(dw));
            }
        }
        unsigned* mo = d_maxk + (size_t)n * 64 + cg * 4;
        unsigned* no = d_mink + (size_t)n * 64 + cg * 4;
        atomicMax(mo+0, enc(hmx.x)); atomicMin(no+0, enc(hmn.x));
        atomicMax(mo+1, enc(hmx.y)); atomicMin(no+1, enc(hmn.y));
        atomicMax(mo+2, enc(hmx.z)); atomicMin(no+2, enc(hmn.z));
        atomicMax(mo+3, enc(hmx.w)); atomicMin(no+3, enc(hmn.w));
    }
    __syncwarp();
    RED16(sum.x); RED16(sum.y); RED16(sum.z); RED16(sum.w);
    RED16(sq.x);  RED16(sq.y);  RED16(sq.z);  RED16(sq.w);
    if (half == 0) {
        atomicAdd(&s_sum[4*cg+0], sum.x); atomicAdd(&s_sum[4*cg+1], sum.y);
        atomicAdd(&s_sum[4*cg+2], sum.z); atomicAdd(&s_sum[4*cg+3], sum.w);
        atomicAdd(&s_sq[4*cg+0], sq.x);   atomicAdd(&s_sq[4*cg+1], sq.y);
        atomicAdd(&s_sq[4*cg+2], sq.z);   atomicAdd(&s_sq[4*cg+3], sq.w);
    }
    __syncthreads();
    if (threadIdx.x < 64)       atomicAdd(&d_sum[threadIdx.x], s_sum[threadIdx.x]);
    else if (threadIdx.x < 128) atomicAdd(&d_sumsq[threadIdx.x - 64], s_sq[threadIdx.x - 64]);
}

__global__ void k_fin(const float* __restrict__ gamma,
                      const float* __restrict__ beta, float invNe) {
    int j = threadIdx.x;
    float mean = d_sum[j] * invNe;
    float var  = d_sumsq[j] * invNe - mean * mean;
    var = var > 0.f ? var : 0.f;
    float s = __ldg(&gamma[j]) * rsqrtf(var + 1e-5f);
    d_scale[j] = s;
    d_bias[j]  = __ldg(&beta[j]) - mean * s;
}

// ---------------------------------------------------------------------------
// Finalize: y = relu(extreme(h)*s + b); monotone affine+relu commutes with
// max. Zero-edge nodes: ±inf/NaN collapse to 0 via fmaxf.
__global__ void k_outfin(float* __restrict__ out, int Nn) {
    int t = blockIdx.x * blockDim.x + threadIdx.x;
    if (t >= Nn * 16) return;
    int cg = t & 15;
    int stray = d_stray;
    float4 sc = *(const float4*)(d_scale + cg * 4);
    float4 bs = *(const float4*)(d_bias + cg * 4);
    uint4 mk = ((const uint4*)d_maxk)[t];
    uint4 nk = ((const uint4*)d_mink)[t];
    float mxx, mxy, mxz, mxw, mnx, mny, mnz, mnw;
    if (stray) {
        mxx = dec(mk.x); mxy = dec(mk.y); mxz = dec(mk.z); mxw = dec(mk.w);
        mnx = dec(nk.x); mny = dec(nk.y); mnz = dec(nk.z); mnw = dec(nk.w);
    } else {
        mxx = __uint_as_float(mk.x); mxy = __uint_as_float(mk.y);
        mxz = __uint_as_float(mk.z); mxw = __uint_as_float(mk.w);
        mnx = __uint_as_float(nk.x); mny = __uint_as_float(nk.y);
        mnz = __uint_as_float(nk.z); mnw = __uint_as_float(nk.w);
    }
    float4 y;
    y.x = fmaxf(fmaf((sc.x >= 0.f) ? mxx : mnx, sc.x, bs.x), 0.f);
    y.y = fmaxf(fmaf((sc.y >= 0.f) ? mxy : mny, sc.y, bs.y), 0.f);
    y.z = fmaxf(fmaf((sc.z >= 0.f) ? mxz : mnz, sc.z, bs.z), 0.f);
    y.w = fmaxf(fmaf((sc.w >= 0.f) ? mxw : mnw, sc.w, bs.w), 0.f);
    ((float4*)out)[t] = y;
}

// ---------------------------------------------------------------------------
extern "C" void kernel_launch(void* const* d_in, const int* in_sizes, int n_in,
                              void* d_out, int out_size) {
    const float* nodep = (const float*)d_in[0];  // (Nn, 3)
    const float* feat  = (const float*)d_in[1];  // (Nn, 64)
    const float* W     = (const float*)d_in[2];  // (64, 67)
    const float* gamma = (const float*)d_in[3];  // (64,)
    const float* beta  = (const float*)d_in[4];  // (64,)
    const void*  edges = d_in[5];                // (Ne, 2) int32 or int64

    int       Nn = in_sizes[0] / 3;
    long long Ne = (long long)in_sizes[5] / 2;
    float*    out = (float*)d_out;
    int kfull = (int)(Ne / Nn);
    int rem   = (int)(Ne % Nn);
    int n4    = (Nn * 64) / 4;

    k_reset <<<1, 64>>>();
    k_conv  <<<1184, 256>>>(edges, Nn, Ne);
    k_init  <<<(n4 + 255) / 256, 256>>>(n4);
    k_pre   <<<(Nn + 63) / 64, 256>>>(nodep, feat, W, Nn);
    k_fast  <<<1184, 256>>>(nodep, W, Nn, kfull, rem);
    k_stray <<<1184, 256>>>(edges, nodep, W, Nn, Ne);
    k_fin   <<<1, 64>>>(gamma, beta, 1.0f / (float)Ne);
    k_outfin<<<(Nn * 16 + 255) / 256, 256>>>(out, Nn);
}

// round 14
// speedup vs baseline: 2.0889x; 1.0120x over previous
#include <cuda_runtime.h>
#include <stdint.h>

#define NMAX 100000

// Scratch (device globals — no allocation allowed)
__device__ float    d_G[NMAX * 64];     // W_f @ f[n] + W_p @ node[n]
__device__ unsigned d_maxk[NMAX * 64];  // fast: raw float bits; stray: enc keys
__device__ unsigned d_mink[NMAX * 64];
__device__ float    d_sum[64];
__device__ float    d_sumsq[64];
__device__ float    d_scale[64];
__device__ float    d_bias[64];
__device__ int      d_is64;
__device__ int      d_stray;

// Order-preserving float<->uint key (stray fallback only)
__device__ __forceinline__ unsigned enc(float f) {
    unsigned u = __float_as_uint(f);
    return (u & 0x80000000u) ? ~u : (u | 0x80000000u);
}
__device__ __forceinline__ float dec(unsigned k) {
    return __uint_as_float((k & 0x80000000u) ? (k ^ 0x80000000u) : ~k);
}

// fma of scalar into float4 channel vector (function, not macro: hygiene)
__device__ __forceinline__ void fma4(float4& acc, float f, const float4& wv) {
    acc.x = fmaf(f, wv.x, acc.x);
    acc.y = fmaf(f, wv.y, acc.y);
    acc.z = fmaf(f, wv.z, acc.z);
    acc.w = fmaf(f, wv.w, acc.w);
}

// ---------------------------------------------------------------------------
// Reset + dtype detect in one tiny kernel. int64 high words (odd int32 slots)
// of indices < 2^31 are zero; int32 layout has random dst values there.
__global__ void k_detect(const int* __restrict__ e32) {
    if (threadIdx.x < 64) { d_sum[threadIdx.x] = 0.f; d_sumsq[threadIdx.x] = 0.f; }
    if (threadIdx.x == 0) {
        int bad = 0;
#pragma unroll
        for (int i = 1; i < 16; i += 2) bad |= e32[i];
        d_is64 = (bad == 0) ? 1 : 0;
        d_stray = 0;
    }
}

// ---------------------------------------------------------------------------
// k_pre: smem-tiled GEMM, 8 nodes x 4 channels per thread (32 fp32 accs).
// Per i4: 4 LDS.128 (weights) + 8 LDG.128 (features, two waves of 4) feed
// 128 FMA -> LDS pressure halved vs the 4-node tile that was L1-bound.
// Block = 256 = 16 cg x 16 slots -> 128 nodes/block.
__global__ void __launch_bounds__(256) k_pre(const float* __restrict__ nodep,
                                             const float* __restrict__ feat,
                                             const float* __restrict__ W, int Nn) {
    __shared__ float Ws[64 * 64];   // Ws[i*64 + c]
    __shared__ float Wp[3 * 64];    // Wp[r*64 + c]
    for (int idx = threadIdx.x; idx < 64 * 67; idx += 256) {
        int c = idx / 67, k = idx - c * 67;
        float v = __ldg(&W[idx]);
        if (k < 64) Ws[k * 64 + c] = v;
        else        Wp[(k - 64) * 64 + c] = v;
    }
    __syncthreads();
    const int cg   = threadIdx.x & 15;    // channels 4cg..4cg+3
    const int slot = threadIdx.x >> 4;    // 16 slots x 8 nodes
    const float4* WsT = (const float4*)Ws;

    int n0 = blockIdx.x * 128 + slot * 8;
    if (n0 >= Nn) return;
    int nn[8];
#pragma unroll
    for (int r = 0; r < 8; r++) nn[r] = min(n0 + r, Nn - 1);
    const float4* fp[8];
#pragma unroll
    for (int r = 0; r < 8; r++) fp[r] = (const float4*)feat + (size_t)nn[r] * 16;

    float4 acc[8];
#pragma unroll
    for (int r = 0; r < 8; r++) acc[r] = make_float4(0.f, 0.f, 0.f, 0.f);

#pragma unroll
    for (int i4 = 0; i4 < 16; i4++) {
        float4 w0 = WsT[(4*i4+0)*16 + cg];
        float4 w1 = WsT[(4*i4+1)*16 + cg];
        float4 w2 = WsT[(4*i4+2)*16 + cg];
        float4 w3 = WsT[(4*i4+3)*16 + cg];
        // wave 1: nodes 0..3
        {
            float4 fa = __ldg(&fp[0][i4]);
            float4 fb = __ldg(&fp[1][i4]);
            float4 fc = __ldg(&fp[2][i4]);
            float4 fd = __ldg(&fp[3][i4]);
            fma4(acc[0], fa.x, w0); fma4(acc[0], fa.y, w1); fma4(acc[0], fa.z, w2); fma4(acc[0], fa.w, w3);
            fma4(acc[1], fb.x, w0); fma4(acc[1], fb.y, w1); fma4(acc[1], fb.z, w2); fma4(acc[1], fb.w, w3);
            fma4(acc[2], fc.x, w0); fma4(acc[2], fc.y, w1); fma4(acc[2], fc.z, w2); fma4(acc[2], fc.w, w3);
            fma4(acc[3], fd.x, w0); fma4(acc[3], fd.y, w1); fma4(acc[3], fd.z, w2); fma4(acc[3], fd.w, w3);
        }
        // wave 2: nodes 4..7
        {
            float4 fa = __ldg(&fp[4][i4]);
            float4 fb = __ldg(&fp[5][i4]);
            float4 fc = __ldg(&fp[6][i4]);
            float4 fd = __ldg(&fp[7][i4]);
            fma4(acc[4], fa.x, w0); fma4(acc[4], fa.y, w1); fma4(acc[4], fa.z, w2); fma4(acc[4], fa.w, w3);
            fma4(acc[5], fb.x, w0); fma4(acc[5], fb.y, w1); fma4(acc[5], fb.z, w2); fma4(acc[5], fb.w, w3);
            fma4(acc[6], fc.x, w0); fma4(acc[6], fc.y, w1); fma4(acc[6], fc.z, w2); fma4(acc[6], fc.w, w3);
            fma4(acc[7], fd.x, w0); fma4(acc[7], fd.y, w1); fma4(acc[7], fd.z, w2); fma4(acc[7], fd.w, w3);
        }
    }
    // + W_p @ node (rank-1 position part)
    float4 wpx = ((const float4*)(Wp +   0))[cg];
    float4 wpy = ((const float4*)(Wp +  64))[cg];
    float4 wpz = ((const float4*)(Wp + 128))[cg];
#pragma unroll
    for (int r = 0; r < 8; r++) {
        float x_ = __ldg(&nodep[3*nn[r]]);
        float y_ = __ldg(&nodep[3*nn[r]+1]);
        float z_ = __ldg(&nodep[3*nn[r]+2]);
        fma4(acc[r], x_, wpx); fma4(acc[r], y_, wpy); fma4(acc[r], z_, wpz);
    }
    float4* G4 = (float4*)d_G;
#pragma unroll
    for (int r = 0; r < 8; r++)
        if (n0 + r < Nn) G4[(size_t)(n0 + r) * 16 + cg] = acc[r];
}

// ---------------------------------------------------------------------------
// FAST edge pass: reads edges DIRECTLY (no compaction pass), verifies the
// structured property src[e]==e%Nn inline (e = n + k*Nn -> src must equal n),
// and assumes it for ownership. If any stray edge is seen, d_stray is set and
// k_fix + k_stray redo everything; on structured data this costs one compare.
// 16 lanes = 1 node; lane cg owns channels 4cg..4cg+3; MLP-16 prefetch.
__global__ void __launch_bounds__(256)
k_fast(const void* __restrict__ edges, const float* __restrict__ nodep,
       const float* __restrict__ W, int Nn, int kfull, int rem) {
    __shared__ float s_sum[64];
    __shared__ float s_sq[64];
    if (threadIdx.x < 64) { s_sum[threadIdx.x] = 0.f; s_sq[threadIdx.x] = 0.f; }
    __syncthreads();
    const int lane = threadIdx.x & 31;
    const int cg   = lane & 15;
    const int is64 = d_is64;
    float4 wx, wy, wz;
    wx.x = __ldg(&W[(4*cg+0)*67+64]); wy.x = __ldg(&W[(4*cg+0)*67+65]); wz.x = __ldg(&W[(4*cg+0)*67+66]);
    wx.y = __ldg(&W[(4*cg+1)*67+64]); wy.y = __ldg(&W[(4*cg+1)*67+65]); wz.y = __ldg(&W[(4*cg+1)*67+66]);
    wx.z = __ldg(&W[(4*cg+2)*67+64]); wy.z = __ldg(&W[(4*cg+2)*67+65]); wz.z = __ldg(&W[(4*cg+2)*67+66]);
    wx.w = __ldg(&W[(4*cg+3)*67+64]); wy.w = __ldg(&W[(4*cg+3)*67+65]); wz.w = __ldg(&W[(4*cg+3)*67+66]);
    const float4* G4 = (const float4*)d_G;
    const float INF = __int_as_float(0x7f800000);
    int gid = (blockIdx.x * blockDim.x + threadIdx.x) >> 4;
    int gs  = (gridDim.x * blockDim.x) >> 4;
    int stray = 0;
    float4 sum = make_float4(0.f,0.f,0.f,0.f);
    float4 sq  = make_float4(0.f,0.f,0.f,0.f);
    for (int n = gid; n < Nn; n += gs) {
        float nx = __ldg(&nodep[3*n]), ny = __ldg(&nodep[3*n+1]), nz = __ldg(&nodep[3*n+2]);
        float4 p;
        p.x = fmaf(wx.x, nx, fmaf(wy.x, ny, wz.x * nz));
        p.y = fmaf(wx.y, nx, fmaf(wy.y, ny, wz.y * nz));
        p.z = fmaf(wx.z, nx, fmaf(wy.z, ny, wz.z * nz));
        p.w = fmaf(wx.w, nx, fmaf(wy.w, ny, wz.w * nz));
        int kmax = kfull + (n < rem);
        float4 mx = make_float4(-INF,-INF,-INF,-INF);
        float4 mn = make_float4( INF, INF, INF, INF);
#define EDGE_BODY(G) { \
            float dx = G.x - p.x, dy = G.y - p.y, dz = G.z - p.z, dw = G.w - p.w; \
            sum.x += dx; sum.y += dy; sum.z += dz; sum.w += dw; \
            sq.x = fmaf(dx,dx,sq.x); sq.y = fmaf(dy,dy,sq.y); \
            sq.z = fmaf(dz,dz,sq.z); sq.w = fmaf(dw,dw,sq.w); \
            mx.x = fmaxf(mx.x,dx); mx.y = fmaxf(mx.y,dy); \
            mx.z = fmaxf(mx.z,dz); mx.w = fmaxf(mx.w,dw); \
            mn.x = fminf(mn.x,dx); mn.y = fminf(mn.y,dy); \
            mn.z = fminf(mn.z,dz); mn.w = fminf(mn.w,dw); }
        if (kmax == 16) {
            int dk[16];
            if (is64) {
#pragma unroll
                for (int k = 0; k < 16; k++) {
                    longlong2 t = __ldg((const longlong2*)edges + (long long)n + (long long)k * Nn);
                    stray |= ((int)t.x != n);
                    dk[k] = (int)t.y;
                }
            } else {
#pragma unroll
                for (int k = 0; k < 16; k++) {
                    int2 t = __ldg((const int2*)edges + (long long)n + (long long)k * Nn);
                    stray |= (t.x != n);
                    dk[k] = t.y;
                }
            }
#pragma unroll
            for (int k = 0; k < 16; k++) {
                float4 g = __ldg(&G4[(size_t)dk[k] * 16 + cg]);
                EDGE_BODY(g);
            }
        } else {
            for (int k = 0; k < kmax; k++) {
                int es, ed;
                if (is64) { longlong2 t = __ldg((const longlong2*)edges + (long long)n + (long long)k * Nn); es = (int)t.x; ed = (int)t.y; }
                else      { int2      t = __ldg((const int2*)edges + (long long)n + (long long)k * Nn);      es = t.x;      ed = t.y; }
                stray |= (es != n);
                float4 g = __ldg(&G4[(size_t)ed * 16 + cg]);
                EDGE_BODY(g);
            }
        }
        ((float4*)d_maxk)[(size_t)n * 16 + cg] = mx;
        ((float4*)d_mink)[(size_t)n * 16 + cg] = mn;
    }
    if (stray) d_stray = 1;
    __syncwarp();
#define RED16(v) v += __shfl_xor_sync(0xFFFFFFFFu, v, 16)
    RED16(sum.x); RED16(sum.y); RED16(sum.z); RED16(sum.w);
    RED16(sq.x);  RED16(sq.y);  RED16(sq.z);  RED16(sq.w);
    if ((lane & 16) == 0) {
        atomicAdd(&s_sum[4*cg+0], sum.x); atomicAdd(&s_sum[4*cg+1], sum.y);
        atomicAdd(&s_sum[4*cg+2], sum.z); atomicAdd(&s_sum[4*cg+3], sum.w);
        atomicAdd(&s_sq[4*cg+0], sq.x);   atomicAdd(&s_sq[4*cg+1], sq.y);
        atomicAdd(&s_sq[4*cg+2], sq.z);   atomicAdd(&s_sq[4*cg+3], sq.w);
    }
    __syncthreads();
    if (threadIdx.x < 64)       atomicAdd(&d_sum[threadIdx.x], s_sum[threadIdx.x]);
    else if (threadIdx.x < 128) atomicAdd(&d_sumsq[threadIdx.x - 64], s_sq[threadIdx.x - 64]);
}

// ---------------------------------------------------------------------------
// Stray repair step 1: reset stats and min/max keys (only if stray detected).
__global__ void k_fix(int n4) {
    if (!d_stray) return;
    int i = blockIdx.x * blockDim.x + threadIdx.x;
    if (i < n4) {
        ((uint4*)d_maxk)[i] = make_uint4(0u, 0u, 0u, 0u);
        ((uint4*)d_mink)[i] = make_uint4(~0u, ~0u, ~0u, ~0u);
    }
    if (blockIdx.x == 0 && threadIdx.x < 64) {
        d_sum[threadIdx.x] = 0.f; d_sumsq[threadIdx.x] = 0.f;
    }
}

// ---------------------------------------------------------------------------
// Stray repair step 2 (arbitrary edges): shuffle-distributed edges, enc-key
// atomics. Dormant on structured data; kept for correctness.
__global__ void __launch_bounds__(256)
k_stray(const void* __restrict__ edges, const float* __restrict__ nodep,
        const float* __restrict__ W, int Nn, long long Ne) {
    if (!d_stray) return;
    __shared__ float s_sum[64];
    __shared__ float s_sq[64];
    if (threadIdx.x < 64) { s_sum[threadIdx.x] = 0.f; s_sq[threadIdx.x] = 0.f; }
    __syncthreads();
    const int lane = threadIdx.x & 31;
    const int cg   = lane & 15;
    const int half = lane & 16;
    const unsigned hm = 0xFFFFu << half;
    const int is64 = d_is64;
    float4 wx, wy, wz;
    wx.x = __ldg(&W[(4*cg+0)*67+64]); wy.x = __ldg(&W[(4*cg+0)*67+65]); wz.x = __ldg(&W[(4*cg+0)*67+66]);
    wx.y = __ldg(&W[(4*cg+1)*67+64]); wy.y = __ldg(&W[(4*cg+1)*67+65]); wz.y = __ldg(&W[(4*cg+1)*67+66]);
    wx.z = __ldg(&W[(4*cg+2)*67+64]); wy.z = __ldg(&W[(4*cg+2)*67+65]); wz.z = __ldg(&W[(4*cg+2)*67+66]);
    wx.w = __ldg(&W[(4*cg+3)*67+64]); wy.w = __ldg(&W[(4*cg+3)*67+65]); wz.w = __ldg(&W[(4*cg+3)*67+66]);
    const float4* G4 = (const float4*)d_G;
    const float INF = __int_as_float(0x7f800000);
    int gid = (blockIdx.x * blockDim.x + threadIdx.x) >> 4;
    int gs  = (gridDim.x * blockDim.x) >> 4;
    float4 sum = make_float4(0.f,0.f,0.f,0.f);
    float4 sq  = make_float4(0.f,0.f,0.f,0.f);
    for (int n = gid; n < Nn; n += gs) {
        long long e = (long long)n + (long long)cg * Nn;
        int es = 0, ed = 0;
        if (e < Ne) {
            if (is64) { longlong2 t = __ldg((const longlong2*)edges + e); es = (int)t.x; ed = (int)t.y; }
            else      { int2      t = __ldg((const int2*)edges + e);      es = t.x;      ed = t.y; }
        }
        float nx = __ldg(&nodep[3*n]), ny = __ldg(&nodep[3*n+1]), nz = __ldg(&nodep[3*n+2]);
        float4 pn;
        pn.x = fmaf(wx.x, nx, fmaf(wy.x, ny, wz.x * nz));
        pn.y = fmaf(wx.y, nx, fmaf(wy.y, ny, wz.y * nz));
        pn.z = fmaf(wx.z, nx, fmaf(wy.z, ny, wz.z * nz));
        pn.w = fmaf(wx.w, nx, fmaf(wy.w, ny, wz.w * nz));
        int kmax = (int)((Ne - n + Nn - 1) / Nn);
        kmax = kmax > 16 ? 16 : kmax;
        float4 hmx = make_float4(-INF,-INF,-INF,-INF);
        float4 hmn = make_float4( INF, INF, INF, INF);
#pragma unroll
        for (int k = 0; k < 16; k++) {
            if (k >= kmax) break;
            int sk = __shfl_sync(hm, es, half + k);
            int dk = __shfl_sync(hm, ed, half + k);
            float4 g = __ldg(&G4[(size_t)dk * 16 + cg]);
            float4 p = pn;
            if (sk != n) {
                float sx = __ldg(&nodep[3*sk]), sy = __ldg(&nodep[3*sk+1]), sz = __ldg(&nodep[3*sk+2]);
                p.x = fmaf(wx.x, sx, fmaf(wy.x, sy, wz.x * sz));
                p.y = fmaf(wx.y, sx, fmaf(wy.y, sy, wz.y * sz));
                p.z = fmaf(wx.z, sx, fmaf(wy.z, sy, wz.z * sz));
                p.w = fmaf(wx.w, sx, fmaf(wy.w, sy, wz.w * sz));
            }
            float dx = g.x - p.x, dy = g.y - p.y, dz = g.z - p.z, dw = g.w - p.w;
            sum.x += dx; sum.y += dy; sum.z += dz; sum.w += dw;
            sq.x = fmaf(dx,dx,sq.x); sq.y = fmaf(dy,dy,sq.y);
            sq.z = fmaf(dz,dz,sq.z); sq.w = fmaf(dw,dw,sq.w);
            if (sk == n) {
                hmx.x = fmaxf(hmx.x,dx); hmx.y = fmaxf(hmx.y,dy);
                hmx.z = fmaxf(hmx.z,dz); hmx.w = fmaxf(hmx.w,dw);
                hmn.x = fminf(hmn.x,dx); hmn.y = fminf(hmn.y,dy);
                hmn.z = fminf(hmn.z,dz); hmn.w = fminf(hmn.w,dw);
            } else {
                unsigned* mo = d_maxk + (size_t)sk * 64 + cg * 4;
                unsigned* no = d_mink + (size_t)sk * 64 + cg * 4;
                atomicMax(mo+0, enc(dx)); atomicMin(no+0, enc(dx));
                atomicMax(mo+1, enc(dy)); atomicMin(no+1, enc(dy));
                atomicMax(mo+2, enc(dz)); atomicMin(no+2, enc(dz));
                atomicMax(mo+3, enc(dw)); atomicMin(no+3, enc(dw));
            }
        }
        unsigned* mo = d_maxk + (size_t)n * 64 + cg * 4;
        unsigned* no = d_mink + (size_t)n * 64 + cg * 4;
        atomicMax(mo+0, enc(hmx.x)); atomicMin(no+0, enc(hmn.x));
        atomicMax(mo+1, enc(hmx.y)); atomicMin(no+1, enc(hmn.y));
        atomicMax(mo+2, enc(hmx.z)); atomicMin(no+2, enc(hmn.z));
        atomicMax(mo+3, enc(hmx.w)); atomicMin(no+3, enc(hmn.w));
    }
    __syncwarp();
    RED16(sum.x); RED16(sum.y); RED16(sum.z); RED16(sum.w);
    RED16(sq.x);  RED16(sq.y);  RED16(sq.z);  RED16(sq.w);
    if (half == 0) {
        atomicAdd(&s_sum[4*cg+0], sum.x); atomicAdd(&s_sum[4*cg+1], sum.y);
        atomicAdd(&s_sum[4*cg+2], sum.z); atomicAdd(&s_sum[4*cg+3], sum.w);
        atomicAdd(&s_sq[4*cg+0], sq.x);   atomicAdd(&s_sq[4*cg+1], sq.y);
        atomicAdd(&s_sq[4*cg+2], sq.z);   atomicAdd(&s_sq[4*cg+3], sq.w);
    }
    __syncthreads();
    if (threadIdx.x < 64)       atomicAdd(&d_sum[threadIdx.x], s_sum[threadIdx.x]);
    else if (threadIdx.x < 128) atomicAdd(&d_sumsq[threadIdx.x - 64], s_sq[threadIdx.x - 64]);
}

__global__ void k_fin(const float* __restrict__ gamma,
                      const float* __restrict__ beta, float invNe) {
    int j = threadIdx.x;
    float mean = d_sum[j] * invNe;
    float var  = d_sumsq[j] * invNe - mean * mean;
    var = var > 0.f ? var : 0.f;
    float s = __ldg(&gamma[j]) * rsqrtf(var + 1e-5f);
    d_scale[j] = s;
    d_bias[j]  = __ldg(&beta[j]) - mean * s;
}

// ---------------------------------------------------------------------------
// Finalize: y = relu(extreme(h)*s + b); monotone affine+relu commutes with
// max. Zero-edge nodes: ±inf/NaN collapse to 0 via fmaxf.
__global__ void k_outfin(float* __restrict__ out, int Nn) {
    int t = blockIdx.x * blockDim.x + threadIdx.x;
    if (t >= Nn * 16) return;
    int cg = t & 15;
    int stray = d_stray;
    float4 sc = *(const float4*)(d_scale + cg * 4);
    float4 bs = *(const float4*)(d_bias + cg * 4);
    uint4 mk = ((const uint4*)d_maxk)[t];
    uint4 nk = ((const uint4*)d_mink)[t];
    float mxx, mxy, mxz, mxw, mnx, mny, mnz, mnw;
    if (stray) {
        mxx = dec(mk.x); mxy = dec(mk.y); mxz = dec(mk.z); mxw = dec(mk.w);
        mnx = dec(nk.x); mny = dec(nk.y); mnz = dec(nk.z); mnw = dec(nk.w);
    } else {
        mxx = __uint_as_float(mk.x); mxy = __uint_as_float(mk.y);
        mxz = __uint_as_float(mk.z); mxw = __uint_as_float(mk.w);
        mnx = __uint_as_float(nk.x); mny = __uint_as_float(nk.y);
        mnz = __uint_as_float(nk.z); mnw = __uint_as_float(nk.w);
    }
    float4 y;
    y.x = fmaxf(fmaf((sc.x >= 0.f) ? mxx : mnx, sc.x, bs.x), 0.f);
    y.y = fmaxf(fmaf((sc.y >= 0.f) ? mxy : mny, sc.y, bs.y), 0.f);
    y.z = fmaxf(fmaf((sc.z >= 0.f) ? mxz : mnz, sc.z, bs.z), 0.f);
    y.w = fmaxf(fmaf((sc.w >= 0.f) ? mxw : mnw, sc.w, bs.w), 0.f);
    ((float4*)out)[t] = y;
}

// ---------------------------------------------------------------------------
extern "C" void kernel_launch(void* const* d_in, const int* in_sizes, int n_in,
                              void* d_out, int out_size) {
    const float* nodep = (const float*)d_in[0];  // (Nn, 3)
    const float* feat  = (const float*)d_in[1];  // (Nn, 64)
    const float* W     = (const float*)d_in[2];  // (64, 67)
    const float* gamma = (const float*)d_in[3];  // (64,)
    const float* beta  = (const float*)d_in[4];  // (64,)
    const void*  edges = d_in[5];                // (Ne, 2) int32 or int64

    int       Nn = in_sizes[0] / 3;
    long long Ne = (long long)in_sizes[5] / 2;
    float*    out = (float*)d_out;
    int kfull = (int)(Ne / Nn);
    if (kfull > 16) kfull = 16;                  // stray path covers overflow
    int rem   = (int)(Ne % Nn);
    int n4    = (Nn * 64) / 4;

    k_detect<<<1, 64>>>((const int*)edges);
    k_pre   <<<(Nn + 127) / 128, 256>>>(nodep, feat, W, Nn);
    k_fast  <<<1184, 256>>>(edges, nodep, W, Nn, kfull, rem);
    k_fix   <<<(n4 + 255) / 256, 256>>>(n4);
    k_stray <<<1184, 256>>>(edges, nodep, W, Nn, Ne);
    k_fin   <<<1, 64>>>(gamma, beta, 1.0f / (float)Ne);
    k_outfin<<<(Nn * 16 + 255) / 256, 256>>>(out, Nn);
}